// round 5
// baseline (speedup 1.0000x reference)
#include <cuda_runtime.h>
#include <cstdint>

// Problem constants
#define B_  4
#define L_  4096
#define H_  1024
#define U_  1024
#define M_  (B_*L_)          // 16384 rows

constexpr int CL = 64;            // scan chunk length
constexpr int NC = L_ / CL;       // 64 chunks per sequence

// ---------------- scratch (device globals; no allocation allowed) -------------
__device__ float g_WiT[(size_t)U_ * H_];   // tf32-rounded Wi      (4 MB)
__device__ float g_WoT[(size_t)H_ * U_];   // tf32-rounded Wo      (4 MB)
__device__ float g_u  [(size_t)M_ * U_];   // u / scanned x        (64 MB)
__device__ float g_v  [(size_t)B_ * NC * U_]; // chunk carries      (1 MB)

// ---------------- helpers ----------------------------------------------------
__device__ __forceinline__ float to_tf32(float x) {
    unsigned u;
    asm("cvt.rna.tf32.f32 %0, %1;" : "=r"(u) : "f"(x));
    return __uint_as_float(u);
}

__device__ __forceinline__ uint32_t smem_u32(const void* p) {
    uint32_t a;
    asm("{ .reg .u64 t; cvta.to.shared.u64 t, %1; cvt.u32.u64 %0, t; }"
        : "=r"(a) : "l"(p));
    return a;
}

__device__ __forceinline__ void cp16(uint32_t saddr, const float* g) {
    asm volatile("cp.async.cg.shared.global [%0], [%1], 16;" :: "r"(saddr), "l"(g));
}
__device__ __forceinline__ void cp_commit() {
    asm volatile("cp.async.commit_group;" ::: "memory");
}

// ldmatrix x4 (b16 view): 4 matrices of 8 rows x 16B. For tf32 data each
// matrix is 8 rows x 4 tf32; thread i receives element (row i>>2, col i&3).
__device__ __forceinline__ void ldsm4(uint32_t* r, uint32_t addr) {
    asm volatile("ldmatrix.sync.aligned.m8n8.x4.shared.b16 {%0,%1,%2,%3}, [%4];"
                 : "=r"(r[0]), "=r"(r[1]), "=r"(r[2]), "=r"(r[3]) : "r"(addr));
}

__device__ __forceinline__ void mma_tf32(float* d, const uint32_t* a, const uint32_t* b) {
    asm volatile(
        "mma.sync.aligned.m16n8k8.row.col.f32.tf32.tf32.f32 "
        "{%0,%1,%2,%3}, {%4,%5,%6,%7}, {%8,%9}, {%0,%1,%2,%3};\n"
        : "+f"(d[0]), "+f"(d[1]), "+f"(d[2]), "+f"(d[3])
        : "r"(a[0]), "r"(a[1]), "r"(a[2]), "r"(a[3]),
          "r"(b[0]), "r"(b[1]));
}

// ---------------- tf32 pre-rounding for weights only -------------------------
__global__ void cvt_tf32_kernel(int sel, const float4* __restrict__ src) {
    float4* dst = (sel == 1) ? reinterpret_cast<float4*>(g_WiT)
                             : reinterpret_cast<float4*>(g_WoT);
    const int n4 = U_ * H_ / 4;
    int i = blockIdx.x * blockDim.x + threadIdx.x;
    int stride = gridDim.x * blockDim.x;
    for (; i < n4; i += stride) {
        float4 v = src[i];
        v.x = to_tf32(v.x); v.y = to_tf32(v.y);
        v.z = to_tf32(v.z); v.w = to_tf32(v.w);
        dst[i] = v;
    }
}

// ---------------- TF32 mma GEMM with ldmatrix: C = A*B^T + bias --------------
// CTA 128x128, BK=32 (=128B rows, one XOR-swizzle atom), 3-stage cp.async,
// 8 warps (4M x 2N), warp tile 32x64, fragments via LDSM, A rounded in regs.
constexpr int TM = 128, TN = 128, BK = 32;
constexpr int KDIM = 1024;
constexpr int NKT  = KDIM / BK;               // 32 chunks
constexpr int NSTAGE = 3;
constexpr int STAGE_A   = TM * BK * 4;        // 16384 B per operand tile
constexpr int STAGE_TOT = 2 * STAGE_A;        // 32768 B
constexpr int GEMM_SMEM = NSTAGE * STAGE_TOT; // 98304 B

__global__ __launch_bounds__(256, 2)
void gemm_tc_kernel(int sel, const float* __restrict__ Aext,
                    const float* __restrict__ bias, float* __restrict__ Cext)
{
    extern __shared__ char smem[];
    const uint32_t sb = smem_u32(smem);
    const int tid = threadIdx.x;
    const int warp = tid >> 5, lane = tid & 31;

    const float* __restrict__ A  = sel ? g_u   : Aext;
    const float* __restrict__ Bw = sel ? g_WoT : g_WiT;
    float* __restrict__ C        = sel ? Cext  : g_u;
    const int bm = blockIdx.y * TM;
    const int bn = blockIdx.x * TN;

    const int wm = (warp >> 1) * 32;      // warp M offset
    const int wn = (warp & 1) * 64;       // warp N offset

    // ---- staging geometry: thread -> (row, 16B-chunk group) ----
    const int srow = tid >> 1;            // 0..127
    const int gb0  = (tid & 1) * 4;       // chunk base 0 or 4
    uint32_t swoff[4];
    #pragma unroll
    for (int i = 0; i < 4; i++)
        swoff[i] = (uint32_t)srow * 128u + ((uint32_t)((gb0 + i) ^ (srow & 7)) << 4);
    const float* Arow = A  + (size_t)(bm + srow) * KDIM;
    const float* Brow = Bw + (size_t)(bn + srow) * KDIM;

    // ---- ldmatrix per-lane invariants ----
    const int lrA  = lane & 15;           // A row-in-16 offset
    const int gsA  = lane >> 4;           // A k-group select (0/1)
    const int lrB  = ((lane & 16) >> 1) + (lane & 7);   // B row offset 0..15
    const int gsB  = (lane >> 3) & 1;     // B k-group select

    float acc[2][8][4];
    #pragma unroll
    for (int mt = 0; mt < 2; mt++)
        #pragma unroll
        for (int nt = 0; nt < 8; nt++)
            #pragma unroll
            for (int i = 0; i < 4; i++) acc[mt][nt][i] = 0.f;

    // ---- prologue: stage chunks 0,1 ----
    #pragma unroll
    for (int c = 0; c < NSTAGE - 1; c++) {
        const uint32_t ao = sb + c * STAGE_TOT;
        #pragma unroll
        for (int i = 0; i < 4; i++) {
            cp16(ao + swoff[i], Arow + c * BK + (gb0 + i) * 4);
            cp16(ao + STAGE_A + swoff[i], Brow + c * BK + (gb0 + i) * 4);
        }
        cp_commit();
    }

    #pragma unroll 1
    for (int kt = 0; kt < NKT; kt++) {
        asm volatile("cp.async.wait_group 1;" ::: "memory");
        __syncthreads();

        // issue loads for chunk kt+2 (overwrites stage read at iter kt-1)
        if (kt + 2 < NKT) {
            const uint32_t ao = sb + ((kt + 2) % NSTAGE) * STAGE_TOT;
            const int k0 = (kt + 2) * BK;
            #pragma unroll
            for (int i = 0; i < 4; i++) {
                cp16(ao + swoff[i], Arow + k0 + (gb0 + i) * 4);
                cp16(ao + STAGE_A + swoff[i], Brow + k0 + (gb0 + i) * 4);
            }
        }
        cp_commit();

        // compute on stage kt%3
        const uint32_t sA = sb + (kt % NSTAGE) * STAGE_TOT;
        const uint32_t sB = sA + STAGE_A;

        #pragma unroll
        for (int ks = 0; ks < 4; ks++) {
            uint32_t afr[2][4], bfr[4][4];
            #pragma unroll
            for (int mt = 0; mt < 2; mt++) {
                const int r = wm + mt * 16 + lrA;
                const uint32_t g = (uint32_t)((ks * 2 + gsA) ^ (lrA & 7));
                ldsm4(afr[mt], sA + (uint32_t)r * 128u + (g << 4));
            }
            #pragma unroll
            for (int p = 0; p < 4; p++) {
                const int r = wn + p * 16 + lrB;
                const uint32_t g = (uint32_t)((ks * 2 + gsB) ^ (lrB & 7));
                ldsm4(bfr[p], sB + (uint32_t)r * 128u + (g << 4));
            }
            // round A fragments to tf32 (rna) in registers
            #pragma unroll
            for (int mt = 0; mt < 2; mt++)
                #pragma unroll
                for (int i = 0; i < 4; i++)
                    asm("cvt.rna.tf32.f32 %0, %1;"
                        : "=r"(afr[mt][i]) : "f"(__uint_as_float(afr[mt][i])));
            #pragma unroll
            for (int mt = 0; mt < 2; mt++)
                #pragma unroll
                for (int nt = 0; nt < 8; nt++)
                    mma_tf32(acc[mt][nt], afr[mt], &bfr[nt >> 1][(nt & 1) * 2]);
        }
    }

    // ---- epilogue: add bias, write fp32 ----
    const int gid = lane >> 2, t4 = lane & 3;
    #pragma unroll
    for (int mt = 0; mt < 2; mt++) {
        const int row = bm + wm + mt * 16 + gid;
        #pragma unroll
        for (int nt = 0; nt < 8; nt++) {
            const int col = bn + wn + nt * 8 + t4 * 2;
            const float b0 = bias[col], b1 = bias[col + 1];
            float2 v0 = make_float2(acc[mt][nt][0] + b0, acc[mt][nt][1] + b1);
            float2 v1 = make_float2(acc[mt][nt][2] + b0, acc[mt][nt][3] + b1);
            *reinterpret_cast<float2*>(&C[(size_t)row * 1024 + col]) = v0;
            *reinterpret_cast<float2*>(&C[(size_t)(row + 8) * 1024 + col]) = v1;
        }
    }
}

// ---------------- scan: h_t = lam*h_{t-1} + u_t, chunked ---------------------
__global__ void scan_local_kernel(const float* __restrict__ plog)
{
    const int g  = blockIdx.x * 256 + threadIdx.x;   // B*NC*U threads
    const int uu = g & (U_ - 1);
    const int c  = (g >> 10) & (NC - 1);
    const int b  = g >> 16;
    const float lam = expf(-expf(plog[uu]));
    float* p = g_u + (size_t)(b * L_ + c * CL) * U_ + uu;
    float h = 0.f;
    #pragma unroll 8
    for (int t = 0; t < CL; t++) {
        float v = p[(size_t)t * U_];
        h = fmaf(lam, h, v);
        p[(size_t)t * U_] = h;
    }
    g_v[(size_t)(b * NC + c) * U_ + uu] = h;
}

__global__ void scan_carry_kernel(const float* __restrict__ plog)
{
    const int g  = blockIdx.x * 256 + threadIdx.x;   // B*U threads
    const int uu = g & (U_ - 1);
    const int b  = g >> 10;
    const float nu   = expf(plog[uu]);
    const float lamC = expf(-(float)CL * nu);
    float* p = g_v + (size_t)b * NC * U_ + uu;
    float carry = 0.f;
    #pragma unroll 1
    for (int c = 0; c < NC; c++) {
        float t = p[(size_t)c * U_];
        p[(size_t)c * U_] = carry;           // exclusive
        carry = fmaf(lamC, carry, t);
    }
}

__global__ void scan_apply_kernel(const float* __restrict__ plog)
{
    const int g  = blockIdx.x * 256 + threadIdx.x;   // B*NC*U threads
    const int uu = g & (U_ - 1);
    const int c  = (g >> 10) & (NC - 1);
    const int b  = g >> 16;
    const float nu  = expf(plog[uu]);
    const float lam = expf(-nu);
    const float gam = expf(plog[U_ + uu]);
    const float carry = g_v[(size_t)(b * NC + c) * U_ + uu];
    float* p = g_u + (size_t)(b * L_ + c * CL) * U_ + uu;
    float pw = lam;
    #pragma unroll 8
    for (int t = 0; t < CL; t++) {
        float v = p[(size_t)t * U_] + pw * carry;   // h_t = local + lam^{t+1}*carry
        p[(size_t)t * U_] = to_tf32(v * gam);
        pw *= lam;
    }
}

// ---------------- launch ------------------------------------------------------
extern "C" void kernel_launch(void* const* d_in, const int* in_sizes, int n_in,
                              void* d_out, int out_size)
{
    const float* inputs = (const float*)d_in[0];
    const float* Wi     = (const float*)d_in[1];
    const float* bi     = (const float*)d_in[2];
    const float* Wo     = (const float*)d_in[3];
    const float* bo     = (const float*)d_in[4];
    const float* plog   = (const float*)d_in[5];
    float* out = (float*)d_out;

    cudaFuncSetAttribute(gemm_tc_kernel,
                         cudaFuncAttributeMaxDynamicSharedMemorySize,
                         GEMM_SMEM);

    // tf32 pre-round weights only (A operands are rounded in-register)
    cvt_tf32_kernel<<<256, 256>>>(1, (const float4*)Wi);
    cvt_tf32_kernel<<<256, 256>>>(2, (const float4*)Wo);

    // GEMM1: u = inputs * Wi^T + bi   -> g_u
    gemm_tc_kernel<<<dim3(U_ / TN, M_ / TM), 256, GEMM_SMEM>>>(0, inputs, bi, nullptr);

    // scan (chunked linear recurrence) + gamma, in place on g_u
    scan_local_kernel<<<(B_ * NC * U_) / 256, 256>>>(plog);
    scan_carry_kernel<<<(B_ * U_) / 256, 256>>>(plog);
    scan_apply_kernel<<<(B_ * NC * U_) / 256, 256>>>(plog);

    // GEMM2: out = x * Wo^T + bo
    gemm_tc_kernel<<<dim3(H_ / TN, M_ / TM), 256, GEMM_SMEM>>>(1, nullptr, bo, out);
}

// round 6
// speedup vs baseline: 1.0245x; 1.0245x over previous
#include <cuda_runtime.h>
#include <cstdint>

// Problem constants
#define B_  4
#define L_  4096
#define H_  1024
#define U_  1024
#define M_  (B_*L_)          // 16384 rows

constexpr int CL = 64;            // scan chunk length
constexpr int NC = L_ / CL;       // 64 chunks per sequence

// ---------------- scratch (device globals; no allocation allowed) -------------
__device__ float g_inT[(size_t)M_ * H_];   // tf32-rounded inputs (64 MB)
__device__ float g_WiT[(size_t)U_ * H_];   // tf32-rounded Wi      (4 MB)
__device__ float g_WoT[(size_t)H_ * U_];   // tf32-rounded Wo      (4 MB)
__device__ float g_u  [(size_t)M_ * U_];   // u / scanned x        (64 MB)
__device__ float g_v  [(size_t)B_ * NC * U_]; // chunk carries      (1 MB)

// ---------------- helpers ----------------------------------------------------
__device__ __forceinline__ float to_tf32(float x) {
    unsigned u;
    asm("cvt.rna.tf32.f32 %0, %1;" : "=r"(u) : "f"(x));
    return __uint_as_float(u);
}

__device__ __forceinline__ uint32_t smem_u32(const void* p) {
    uint32_t a;
    asm("{ .reg .u64 t; cvta.to.shared.u64 t, %1; cvt.u32.u64 %0, t; }"
        : "=r"(a) : "l"(p));
    return a;
}

__device__ __forceinline__ void cp16(uint32_t saddr, const float* g) {
    asm volatile("cp.async.cg.shared.global [%0], [%1], 16;" :: "r"(saddr), "l"(g));
}
__device__ __forceinline__ void cp_commit() {
    asm volatile("cp.async.commit_group;" ::: "memory");
}

// ldmatrix x4 (b16 view): 4 matrices of 8 rows x 16B. For tf32 data each
// matrix is 8 rows x 4 tf32; lane i of a matrix gets element (i>>2, i&3).
__device__ __forceinline__ void ldsm4(uint32_t* r, uint32_t addr) {
    asm volatile("ldmatrix.sync.aligned.m8n8.x4.shared.b16 {%0,%1,%2,%3}, [%4];"
                 : "=r"(r[0]), "=r"(r[1]), "=r"(r[2]), "=r"(r[3]) : "r"(addr));
}

__device__ __forceinline__ void mma_tf32(float* d, const uint32_t* a, const uint32_t* b) {
    asm volatile(
        "mma.sync.aligned.m16n8k8.row.col.f32.tf32.tf32.f32 "
        "{%0,%1,%2,%3}, {%4,%5,%6,%7}, {%8,%9}, {%0,%1,%2,%3};\n"
        : "+f"(d[0]), "+f"(d[1]), "+f"(d[2]), "+f"(d[3])
        : "r"(a[0]), "r"(a[1]), "r"(a[2]), "r"(a[3]),
          "r"(b[0]), "r"(b[1]));
}

// ---------------- tf32 pre-rounding -------------------------------------------
__global__ void cvt_tf32_kernel(int sel, const float4* __restrict__ src) {
    float4* dst;
    int n4;
    if (sel == 0)      { dst = reinterpret_cast<float4*>(g_inT); n4 = (int)((size_t)M_ * H_ / 4); }
    else if (sel == 1) { dst = reinterpret_cast<float4*>(g_WiT); n4 = U_ * H_ / 4; }
    else               { dst = reinterpret_cast<float4*>(g_WoT); n4 = H_ * U_ / 4; }
    int i = blockIdx.x * blockDim.x + threadIdx.x;
    int stride = gridDim.x * blockDim.x;
    for (; i < n4; i += stride) {
        float4 v = src[i];
        v.x = to_tf32(v.x); v.y = to_tf32(v.y);
        v.z = to_tf32(v.z); v.w = to_tf32(v.w);
        dst[i] = v;
    }
}

// ---------------- TF32 mma GEMM with ldmatrix: C = A*B^T + bias --------------
// CTA 128x128, BK=32 (=128B rows, one XOR-swizzle atom), 3-stage cp.async,
// 8 warps (4M x 2N), warp tile 32x64, fragments via LDSM (no in-loop cvt).
constexpr int TM = 128, TN = 128, BK = 32;
constexpr int KDIM = 1024;
constexpr int NKT  = KDIM / BK;               // 32 chunks
constexpr int NSTAGE = 3;
constexpr int STAGE_A   = TM * BK * 4;        // 16384 B per operand tile
constexpr int STAGE_TOT = 2 * STAGE_A;        // 32768 B
constexpr int GEMM_SMEM = NSTAGE * STAGE_TOT; // 98304 B

__global__ __launch_bounds__(256, 2)
void gemm_tc_kernel(int sel, const float* __restrict__ bias, float* __restrict__ Cext)
{
    extern __shared__ char smem[];
    const uint32_t sb = smem_u32(smem);
    const int tid = threadIdx.x;
    const int warp = tid >> 5, lane = tid & 31;

    const float* __restrict__ A  = sel ? g_u   : g_inT;
    const float* __restrict__ Bw = sel ? g_WoT : g_WiT;
    float* __restrict__ C        = sel ? Cext  : g_u;
    const int bm = blockIdx.y * TM;
    const int bn = blockIdx.x * TN;

    const int wm = (warp >> 1) * 32;      // warp M offset
    const int wn = (warp & 1) * 64;       // warp N offset

    // ---- staging geometry: thread -> (row, 16B-chunk group) ----
    const int srow = tid >> 1;            // 0..127
    const int gb0  = (tid & 1) * 4;       // chunk base 0 or 4
    uint32_t swoff[4];
    #pragma unroll
    for (int i = 0; i < 4; i++)
        swoff[i] = (uint32_t)srow * 128u + ((uint32_t)((gb0 + i) ^ (srow & 7)) << 4);
    const float* Arow = A  + (size_t)(bm + srow) * KDIM;
    const float* Brow = Bw + (size_t)(bn + srow) * KDIM;

    // ---- ldmatrix per-lane invariants ----
    const int lrA  = lane & 15;           // A row-in-16 offset
    const int gsA  = lane >> 4;           // A k-group select (0/1)
    const int lrB  = ((lane & 16) >> 1) + (lane & 7);   // B row offset 0..15
    const int gsB  = (lane >> 3) & 1;     // B k-group select

    float acc[2][8][4];
    #pragma unroll
    for (int mt = 0; mt < 2; mt++)
        #pragma unroll
        for (int nt = 0; nt < 8; nt++)
            #pragma unroll
            for (int i = 0; i < 4; i++) acc[mt][nt][i] = 0.f;

    // ---- prologue: stage chunks 0,1 ----
    #pragma unroll
    for (int c = 0; c < NSTAGE - 1; c++) {
        const uint32_t ao = sb + c * STAGE_TOT;
        #pragma unroll
        for (int i = 0; i < 4; i++) {
            cp16(ao + swoff[i], Arow + c * BK + (gb0 + i) * 4);
            cp16(ao + STAGE_A + swoff[i], Brow + c * BK + (gb0 + i) * 4);
        }
        cp_commit();
    }

    #pragma unroll 1
    for (int kt = 0; kt < NKT; kt++) {
        asm volatile("cp.async.wait_group 1;" ::: "memory");
        __syncthreads();

        // issue loads for chunk kt+2 (into stage freed at end of iter kt-1)
        if (kt + 2 < NKT) {
            const uint32_t ao = sb + ((kt + 2) % NSTAGE) * STAGE_TOT;
            const int k0 = (kt + 2) * BK;
            #pragma unroll
            for (int i = 0; i < 4; i++) {
                cp16(ao + swoff[i], Arow + k0 + (gb0 + i) * 4);
                cp16(ao + STAGE_A + swoff[i], Brow + k0 + (gb0 + i) * 4);
            }
        }
        cp_commit();

        // compute on stage kt%3
        const uint32_t sA = sb + (kt % NSTAGE) * STAGE_TOT;
        const uint32_t sB = sA + STAGE_A;

        #pragma unroll
        for (int ks = 0; ks < 4; ks++) {
            uint32_t afr[2][4], bfr[4][4];
            #pragma unroll
            for (int mt = 0; mt < 2; mt++) {
                const int r = wm + mt * 16 + lrA;
                const uint32_t g = (uint32_t)((ks * 2 + gsA) ^ (lrA & 7));
                ldsm4(afr[mt], sA + (uint32_t)r * 128u + (g << 4));
            }
            #pragma unroll
            for (int p = 0; p < 4; p++) {
                const int r = wn + p * 16 + lrB;
                const uint32_t g = (uint32_t)((ks * 2 + gsB) ^ (lrB & 7));
                ldsm4(bfr[p], sB + (uint32_t)r * 128u + (g << 4));
            }
            #pragma unroll
            for (int mt = 0; mt < 2; mt++)
                #pragma unroll
                for (int nt = 0; nt < 8; nt++)
                    mma_tf32(acc[mt][nt], afr[mt], &bfr[nt >> 1][(nt & 1) * 2]);
        }
    }

    // ---- epilogue: add bias, write fp32 ----
    const int gid = lane >> 2, t4 = lane & 3;
    #pragma unroll
    for (int mt = 0; mt < 2; mt++) {
        const int row = bm + wm + mt * 16 + gid;
        #pragma unroll
        for (int nt = 0; nt < 8; nt++) {
            const int col = bn + wn + nt * 8 + t4 * 2;
            const float b0 = bias[col], b1 = bias[col + 1];
            float2 v0 = make_float2(acc[mt][nt][0] + b0, acc[mt][nt][1] + b1);
            float2 v1 = make_float2(acc[mt][nt][2] + b0, acc[mt][nt][3] + b1);
            *reinterpret_cast<float2*>(&C[(size_t)row * 1024 + col]) = v0;
            *reinterpret_cast<float2*>(&C[(size_t)(row + 8) * 1024 + col]) = v1;
        }
    }
}

// ---------------- scan: h_t = lam*h_{t-1} + u_t, chunked ---------------------
// K1: chunk aggregates only (no write-back of locals) -> g_v
__global__ void scan_agg_kernel(const float* __restrict__ plog)
{
    const int g  = blockIdx.x * 256 + threadIdx.x;   // B*NC*U threads
    const int uu = g & (U_ - 1);
    const int c  = (g >> 10) & (NC - 1);
    const int b  = g >> 16;
    const float lam = expf(-expf(plog[uu]));
    const float* p = g_u + (size_t)(b * L_ + c * CL) * U_ + uu;
    float h = 0.f;
    #pragma unroll 8
    for (int t = 0; t < CL; t++)
        h = fmaf(lam, h, p[(size_t)t * U_]);
    g_v[(size_t)(b * NC + c) * U_ + uu] = h;
}

// K2: exclusive scan of chunk aggregates along the chunk axis (per b,u).
__global__ void scan_carry_kernel(const float* __restrict__ plog)
{
    const int g  = blockIdx.x * 256 + threadIdx.x;   // B*U threads
    const int uu = g & (U_ - 1);
    const int b  = g >> 10;
    const float nu   = expf(plog[uu]);
    const float lamC = expf(-(float)CL * nu);
    float* p = g_v + (size_t)b * NC * U_ + uu;
    float carry = 0.f;
    #pragma unroll 1
    for (int c = 0; c < NC; c++) {
        float t = p[(size_t)c * U_];
        p[(size_t)c * U_] = carry;           // exclusive (state at chunk start)
        carry = fmaf(lamC, carry, t);
    }
}

// K3: redo local scan seeded with carry, multiply gamma, round to tf32.
__global__ void scan_apply_kernel(const float* __restrict__ plog)
{
    const int g  = blockIdx.x * 256 + threadIdx.x;   // B*NC*U threads
    const int uu = g & (U_ - 1);
    const int c  = (g >> 10) & (NC - 1);
    const int b  = g >> 16;
    const float lam = expf(-expf(plog[uu]));
    const float gam = expf(plog[U_ + uu]);
    float h = g_v[(size_t)(b * NC + c) * U_ + uu];   // state before chunk
    float* p = g_u + (size_t)(b * L_ + c * CL) * U_ + uu;
    #pragma unroll 8
    for (int t = 0; t < CL; t++) {
        h = fmaf(lam, h, p[(size_t)t * U_]);
        p[(size_t)t * U_] = to_tf32(h * gam);
    }
}

// ---------------- launch ------------------------------------------------------
extern "C" void kernel_launch(void* const* d_in, const int* in_sizes, int n_in,
                              void* d_out, int out_size)
{
    const float* inputs = (const float*)d_in[0];
    const float* Wi     = (const float*)d_in[1];
    const float* bi     = (const float*)d_in[2];
    const float* Wo     = (const float*)d_in[3];
    const float* bo     = (const float*)d_in[4];
    const float* plog   = (const float*)d_in[5];
    float* out = (float*)d_out;

    cudaFuncSetAttribute(gemm_tc_kernel,
                         cudaFuncAttributeMaxDynamicSharedMemorySize,
                         GEMM_SMEM);

    // tf32 pre-rounding (off the GEMM critical path)
    cvt_tf32_kernel<<<2048, 256>>>(0, (const float4*)inputs);
    cvt_tf32_kernel<<<256, 256>>>(1, (const float4*)Wi);
    cvt_tf32_kernel<<<256, 256>>>(2, (const float4*)Wo);

    // GEMM1: u = inputs * Wi^T + bi   -> g_u
    gemm_tc_kernel<<<dim3(U_ / TN, M_ / TM), 256, GEMM_SMEM>>>(0, bi, nullptr);

    // scan (chunked linear recurrence) + gamma, in place on g_u
    scan_agg_kernel<<<(B_ * NC * U_) / 256, 256>>>(plog);
    scan_carry_kernel<<<(B_ * U_) / 256, 256>>>(plog);
    scan_apply_kernel<<<(B_ * NC * U_) / 256, 256>>>(plog);

    // GEMM2: out = x * Wo^T + bo
    gemm_tc_kernel<<<dim3(H_ / TN, M_ / TM), 256, GEMM_SMEM>>>(1, bo, out);
}

// round 7
// speedup vs baseline: 1.6739x; 1.6338x over previous
#include <cuda_runtime.h>
#include <cuda_fp16.h>
#include <cstdint>

// Problem constants
#define B_  4
#define L_  4096
#define H_  1024
#define U_  1024
#define M_  (B_*L_)          // 16384 rows

constexpr int CL = 64;            // scan chunk length
constexpr int NC = L_ / CL;       // 64 chunks per sequence

// ---------------- scratch (device globals; no allocation allowed) -------------
__device__ __half g_inH[(size_t)M_ * H_];   // fp16 inputs          (32 MB)
__device__ __half g_WiH[(size_t)U_ * H_];   // fp16 Wi              (2 MB)
__device__ __half g_WoH[(size_t)H_ * U_];   // fp16 Wo              (2 MB)
__device__ __half g_uh [(size_t)M_ * U_];   // fp16 scanned x       (32 MB)
__device__ float  g_u  [(size_t)M_ * U_];   // fp32 u (pre-scan)    (64 MB)
__device__ float  g_v  [(size_t)B_ * NC * U_]; // chunk carries      (1 MB)

// ---------------- helpers ----------------------------------------------------
__device__ __forceinline__ uint32_t smem_u32(const void* p) {
    uint32_t a;
    asm("{ .reg .u64 t; cvta.to.shared.u64 t, %1; cvt.u32.u64 %0, t; }"
        : "=r"(a) : "l"(p));
    return a;
}

__device__ __forceinline__ void cp16(uint32_t saddr, const void* g) {
    asm volatile("cp.async.cg.shared.global [%0], [%1], 16;" :: "r"(saddr), "l"(g));
}
__device__ __forceinline__ void cp_commit() {
    asm volatile("cp.async.commit_group;" ::: "memory");
}

// ldmatrix x4: 4 matrices of 8 rows x 16B (8 halves).
__device__ __forceinline__ void ldsm4(uint32_t* r, uint32_t addr) {
    asm volatile("ldmatrix.sync.aligned.m8n8.x4.shared.b16 {%0,%1,%2,%3}, [%4];"
                 : "=r"(r[0]), "=r"(r[1]), "=r"(r[2]), "=r"(r[3]) : "r"(addr));
}

__device__ __forceinline__ void mma_f16(float* d, const uint32_t* a, const uint32_t* b) {
    asm volatile(
        "mma.sync.aligned.m16n8k16.row.col.f32.f16.f16.f32 "
        "{%0,%1,%2,%3}, {%4,%5,%6,%7}, {%8,%9}, {%0,%1,%2,%3};\n"
        : "+f"(d[0]), "+f"(d[1]), "+f"(d[2]), "+f"(d[3])
        : "r"(a[0]), "r"(a[1]), "r"(a[2]), "r"(a[3]),
          "r"(b[0]), "r"(b[1]));
}

// ---------------- fp16 conversion pass ---------------------------------------
__global__ void cvt_f16_kernel(int sel, const float4* __restrict__ src) {
    __half* dst;
    size_t n8;
    if (sel == 0)      { dst = g_inH; n8 = (size_t)M_ * H_ / 8; }
    else if (sel == 1) { dst = g_WiH; n8 = (size_t)U_ * H_ / 8; }
    else               { dst = g_WoH; n8 = (size_t)H_ * U_ / 8; }
    size_t i = (size_t)blockIdx.x * blockDim.x + threadIdx.x;
    size_t stride = (size_t)gridDim.x * blockDim.x;
    for (; i < n8; i += stride) {
        float4 a = src[2 * i], b = src[2 * i + 1];
        __half2 h[4];
        h[0] = __floats2half2_rn(a.x, a.y);
        h[1] = __floats2half2_rn(a.z, a.w);
        h[2] = __floats2half2_rn(b.x, b.y);
        h[3] = __floats2half2_rn(b.z, b.w);
        reinterpret_cast<uint4*>(dst)[i] = *reinterpret_cast<uint4*>(h);
    }
}

// ---------------- FP16 mma GEMM with ldmatrix: C = A*B^T + bias --------------
// CTA 128x128, BK=64 halves (=128B rows, one XOR-swizzle atom), 3-stage
// cp.async, 8 warps (4M x 2N), warp tile 32x64, mma m16n8k16, fp32 accum.
constexpr int TM = 128, TN = 128, BKH = 64;   // BKH in halves
constexpr int KDIM = 1024;                    // halves
constexpr int NKT  = KDIM / BKH;              // 16 chunks
constexpr int NSTAGE = 3;
constexpr int STAGE_A   = TM * 128;           // 16384 B per operand tile
constexpr int STAGE_TOT = 2 * STAGE_A;        // 32768 B
constexpr int GEMM_SMEM = NSTAGE * STAGE_TOT; // 98304 B

__global__ __launch_bounds__(256, 2)
void gemm_f16_kernel(int sel, const float* __restrict__ bias, float* __restrict__ Cext)
{
    extern __shared__ char smem[];
    const uint32_t sb = smem_u32(smem);
    const int tid = threadIdx.x;
    const int warp = tid >> 5, lane = tid & 31;

    const __half* __restrict__ A  = sel ? g_uh  : g_inH;
    const __half* __restrict__ Bw = sel ? g_WoH : g_WiH;
    float* __restrict__ C         = sel ? Cext  : g_u;
    const int bm = blockIdx.y * TM;
    const int bn = blockIdx.x * TN;

    const int wm = (warp >> 1) * 32;      // warp M offset
    const int wn = (warp & 1) * 64;       // warp N offset

    // ---- staging: thread -> (row, 16B-chunk group); rows are 128B ----
    const int srow = tid >> 1;            // 0..127
    const int gb0  = (tid & 1) * 4;       // chunk base 0 or 4
    uint32_t swoff[4];
    #pragma unroll
    for (int i = 0; i < 4; i++)
        swoff[i] = (uint32_t)srow * 128u + ((uint32_t)((gb0 + i) ^ (srow & 7)) << 4);
    const __half* Arow = A  + (size_t)(bm + srow) * KDIM;
    const __half* Brow = Bw + (size_t)(bn + srow) * KDIM;

    // ---- ldmatrix per-lane invariants (A x4 and B x4, non-trans) ----
    const int lrA  = lane & 15;           // A: matrices 0,1 rows m0..15
    const int gsA  = lane >> 4;           // A: k-chunk select (0/1 within k16)
    const int lrB  = ((lane & 16) >> 1) + (lane & 7);   // B row offset 0..15
    const int gsB  = (lane >> 3) & 1;     // B k-chunk select

    float acc[2][8][4];
    #pragma unroll
    for (int mt = 0; mt < 2; mt++)
        #pragma unroll
        for (int nt = 0; nt < 8; nt++)
            #pragma unroll
            for (int i = 0; i < 4; i++) acc[mt][nt][i] = 0.f;

    // ---- prologue: stage chunks 0,1 ----
    #pragma unroll
    for (int c = 0; c < NSTAGE - 1; c++) {
        const uint32_t ao = sb + c * STAGE_TOT;
        #pragma unroll
        for (int i = 0; i < 4; i++) {
            cp16(ao + swoff[i], Arow + c * BKH + (gb0 + i) * 8);
            cp16(ao + STAGE_A + swoff[i], Brow + c * BKH + (gb0 + i) * 8);
        }
        cp_commit();
    }

    #pragma unroll 1
    for (int kt = 0; kt < NKT; kt++) {
        asm volatile("cp.async.wait_group 1;" ::: "memory");
        __syncthreads();

        if (kt + 2 < NKT) {
            const uint32_t ao = sb + ((kt + 2) % NSTAGE) * STAGE_TOT;
            const int k0 = (kt + 2) * BKH;
            #pragma unroll
            for (int i = 0; i < 4; i++) {
                cp16(ao + swoff[i], Arow + k0 + (gb0 + i) * 8);
                cp16(ao + STAGE_A + swoff[i], Brow + k0 + (gb0 + i) * 8);
            }
        }
        cp_commit();

        const uint32_t sA = sb + (kt % NSTAGE) * STAGE_TOT;
        const uint32_t sB = sA + STAGE_A;

        #pragma unroll
        for (int ks = 0; ks < 4; ks++) {          // 4 x k16 per 64-half chunk
            uint32_t afr[2][4], bfr[4][4];
            #pragma unroll
            for (int mt = 0; mt < 2; mt++) {
                const int r = wm + mt * 16 + lrA;
                const uint32_t g = (uint32_t)((ks * 2 + gsA) ^ (lrA & 7));
                ldsm4(afr[mt], sA + (uint32_t)r * 128u + (g << 4));
            }
            #pragma unroll
            for (int p = 0; p < 4; p++) {
                const int r = wn + p * 16 + lrB;
                const uint32_t g = (uint32_t)((ks * 2 + gsB) ^ (lrB & 7));
                ldsm4(bfr[p], sB + (uint32_t)r * 128u + (g << 4));
            }
            #pragma unroll
            for (int mt = 0; mt < 2; mt++)
                #pragma unroll
                for (int nt = 0; nt < 8; nt++)
                    mma_f16(acc[mt][nt], afr[mt], &bfr[nt >> 1][(nt & 1) * 2]);
        }
    }

    // ---- epilogue: add bias, write fp32 ----
    const int gid = lane >> 2, t4 = lane & 3;
    #pragma unroll
    for (int mt = 0; mt < 2; mt++) {
        const int row = bm + wm + mt * 16 + gid;
        #pragma unroll
        for (int nt = 0; nt < 8; nt++) {
            const int col = bn + wn + nt * 8 + t4 * 2;
            const float b0 = bias[col], b1 = bias[col + 1];
            float2 v0 = make_float2(acc[mt][nt][0] + b0, acc[mt][nt][1] + b1);
            float2 v1 = make_float2(acc[mt][nt][2] + b0, acc[mt][nt][3] + b1);
            *reinterpret_cast<float2*>(&C[(size_t)row * 1024 + col]) = v0;
            *reinterpret_cast<float2*>(&C[(size_t)(row + 8) * 1024 + col]) = v1;
        }
    }
}

// ---------------- scan: h_t = lam*h_{t-1} + u_t, chunked (fp32) ---------------
// K1: chunk aggregates only -> g_v
__global__ void scan_agg_kernel(const float* __restrict__ plog)
{
    const int g  = blockIdx.x * 256 + threadIdx.x;   // B*NC*U threads
    const int uu = g & (U_ - 1);
    const int c  = (g >> 10) & (NC - 1);
    const int b  = g >> 16;
    const float lam = expf(-expf(plog[uu]));
    const float* p = g_u + (size_t)(b * L_ + c * CL) * U_ + uu;
    float h = 0.f;
    #pragma unroll 8
    for (int t = 0; t < CL; t++)
        h = fmaf(lam, h, p[(size_t)t * U_]);
    g_v[(size_t)(b * NC + c) * U_ + uu] = h;
}

// K2: exclusive scan of chunk aggregates along the chunk axis (per b,u).
__global__ void scan_carry_kernel(const float* __restrict__ plog)
{
    const int g  = blockIdx.x * 256 + threadIdx.x;   // B*U threads
    const int uu = g & (U_ - 1);
    const int b  = g >> 10;
    const float nu   = expf(plog[uu]);
    const float lamC = expf(-(float)CL * nu);
    float* p = g_v + (size_t)b * NC * U_ + uu;
    float carry = 0.f;
    #pragma unroll 1
    for (int c = 0; c < NC; c++) {
        float t = p[(size_t)c * U_];
        p[(size_t)c * U_] = carry;           // exclusive (state at chunk start)
        carry = fmaf(lamC, carry, t);
    }
}

// K3: redo local scan seeded with carry, * gamma, emit fp16 operand for GEMM2.
__global__ void scan_apply_kernel(const float* __restrict__ plog)
{
    const int g  = blockIdx.x * 256 + threadIdx.x;   // B*NC*U threads
    const int uu = g & (U_ - 1);
    const int c  = (g >> 10) & (NC - 1);
    const int b  = g >> 16;
    const float lam = expf(-expf(plog[uu]));
    const float gam = expf(plog[U_ + uu]);
    float h = g_v[(size_t)(b * NC + c) * U_ + uu];   // state before chunk
    const float* p = g_u + (size_t)(b * L_ + c * CL) * U_ + uu;
    __half*      q = g_uh + (size_t)(b * L_ + c * CL) * U_ + uu;
    #pragma unroll 8
    for (int t = 0; t < CL; t++) {
        h = fmaf(lam, h, p[(size_t)t * U_]);
        q[(size_t)t * U_] = __float2half_rn(h * gam);
    }
}

// ---------------- launch ------------------------------------------------------
extern "C" void kernel_launch(void* const* d_in, const int* in_sizes, int n_in,
                              void* d_out, int out_size)
{
    const float* inputs = (const float*)d_in[0];
    const float* Wi     = (const float*)d_in[1];
    const float* bi     = (const float*)d_in[2];
    const float* Wo     = (const float*)d_in[3];
    const float* bo     = (const float*)d_in[4];
    const float* plog   = (const float*)d_in[5];
    float* out = (float*)d_out;

    cudaFuncSetAttribute(gemm_f16_kernel,
                         cudaFuncAttributeMaxDynamicSharedMemorySize,
                         GEMM_SMEM);

    // fp16 conversion (off the GEMM critical path)
    cvt_f16_kernel<<<2048, 256>>>(0, (const float4*)inputs);
    cvt_f16_kernel<<<256, 256>>>(1, (const float4*)Wi);
    cvt_f16_kernel<<<256, 256>>>(2, (const float4*)Wo);

    // GEMM1: u = inputs * Wi^T + bi   -> g_u (fp32)
    gemm_f16_kernel<<<dim3(U_ / TN, M_ / TM), 256, GEMM_SMEM>>>(0, bi, nullptr);

    // scan (chunked linear recurrence) + gamma -> g_uh (fp16)
    scan_agg_kernel<<<(B_ * NC * U_) / 256, 256>>>(plog);
    scan_carry_kernel<<<(B_ * U_) / 256, 256>>>(plog);
    scan_apply_kernel<<<(B_ * NC * U_) / 256, 256>>>(plog);

    // GEMM2: out = x * Wo^T + bo
    gemm_f16_kernel<<<dim3(H_ / TN, M_ / TM), 256, GEMM_SMEM>>>(1, bo, out);
}